// round 11
// baseline (speedup 1.0000x reference)
#include <cuda_runtime.h>
#include <math.h>

// Problem constants
#define BATCH 8
#define HEADS 8
#define SEQ   1024
#define DM    512
#define DEPTH 64
#define MROWS (BATCH*SEQ)          // 8192
#define OUT_OFF (BATCH*SEQ*DM)     // out region floats, then attn region

typedef unsigned long long u64;

// Packed dual-FMA: acc.{lo,hi} += a.{lo,hi} * b.{lo,hi}  (full fp32 precision)
__device__ __forceinline__ void ffma2(u64 &acc, u64 a, u64 b) {
    asm("fma.rn.f32x2 %0, %1, %2, %3;" : "=l"(acc) : "l"(a), "l"(b), "l"(acc));
}
union U2F { u64 u; float2 f; };
union U4 { float4 f[4]; u64 u[8]; };
union U2 { float4 f[2]; u64 u[4]; };

// Scratch (device globals; no runtime allocation allowed)
__device__ float g_q [BATCH*HEADS*SEQ*DEPTH];   // [bh][s][d]
__device__ float g_kt[BATCH*HEADS*DEPTH*SEQ];   // [bh][d][s]
__device__ float g_v [BATCH*HEADS*SEQ*DEPTH];   // [bh][s][d]
__device__ float g_x [BATCH*SEQ*DM];            // [b*s][h*64+d]

// ---------------------------------------------------------------------------
// Projection / output GEMM: C[8192,512] = X[8192,512] @ W[512,512] + bias
// mode 0 -> g_q; 1 -> g_kt (transposed); 2 -> g_v; 3 -> reads g_x, writes out
// 128x128 tile, BK=16, 256 threads, 8x8 microtile via f32x2 (acc pairs over j).
// A smem tile stored DUPLICATED (each value twice) so a-splats load directly.
// ---------------------------------------------------------------------------
__global__ __launch_bounds__(256) void proj_gemm(
    const float* __restrict__ Xarg, const float* __restrict__ W,
    const float* __restrict__ bias, float* __restrict__ out, int mode)
{
    __shared__ float Asd[16][264];   // duplicated: [k][2r],[2r+1] = A[r][k]
    __shared__ float Bs[16][128];

    const float* X = (mode == 3) ? (const float*)g_x : Xarg;

    const int tid = threadIdx.x;
    const int tx = tid & 15, ty = tid >> 4;
    const int rowBase = blockIdx.y * 128;
    const int colBase = blockIdx.x * 128;

    u64 acc[8][4];
    #pragma unroll
    for (int i = 0; i < 8; i++)
        #pragma unroll
        for (int j = 0; j < 4; j++) acc[i][j] = 0ull;

    for (int k0 = 0; k0 < DM; k0 += 16) {
        #pragma unroll
        for (int i = 0; i < 2; i++) {
            int idx = tid * 2 + i;            // 0..511
            int r   = idx >> 2;               // 0..127
            int c4  = idx & 3;                // 0..3
            float4 v = *(const float4*)&X[(size_t)(rowBase + r) * DM + k0 + c4 * 4];
            *(float2*)&Asd[c4*4+0][2*r] = make_float2(v.x, v.x);
            *(float2*)&Asd[c4*4+1][2*r] = make_float2(v.y, v.y);
            *(float2*)&Asd[c4*4+2][2*r] = make_float2(v.z, v.z);
            *(float2*)&Asd[c4*4+3][2*r] = make_float2(v.w, v.w);
        }
        #pragma unroll
        for (int i = 0; i < 2; i++) {
            int idx = tid * 2 + i;
            int kk  = idx >> 5;
            int c4  = idx & 31;
            *(float4*)&Bs[kk][c4*4] =
                *(const float4*)&W[(size_t)(k0 + kk) * DM + colBase + c4 * 4];
        }
        __syncthreads();

        #pragma unroll
        for (int kk = 0; kk < 16; kk++) {
            U4 Aq; U2 Bq;
            Aq.f[0] = *(const float4*)&Asd[kk][ty*16 +  0];
            Aq.f[1] = *(const float4*)&Asd[kk][ty*16 +  4];
            Aq.f[2] = *(const float4*)&Asd[kk][ty*16 +  8];
            Aq.f[3] = *(const float4*)&Asd[kk][ty*16 + 12];
            Bq.f[0] = *(const float4*)&Bs[kk][tx*8];
            Bq.f[1] = *(const float4*)&Bs[kk][tx*8+4];
            #pragma unroll
            for (int i = 0; i < 8; i++)
                #pragma unroll
                for (int jp = 0; jp < 4; jp++)
                    ffma2(acc[i][jp], Aq.u[i], Bq.u[jp]);
        }
        __syncthreads();
    }

    #pragma unroll
    for (int i = 0; i < 8; i++) {
        int m  = rowBase + ty * 8 + i;
        int bb = m >> 10, s = m & 1023;
        #pragma unroll
        for (int jp = 0; jp < 4; jp++) {
            U2F c; c.u = acc[i][jp];
            #pragma unroll
            for (int hh = 0; hh < 2; hh++) {
                int n = colBase + tx * 8 + 2*jp + hh;
                float v = (hh ? c.f.y : c.f.x) + bias[n];
                int h = n >> 6, d = n & 63;
                int bh = bb * HEADS + h;
                if      (mode == 0) g_q [((size_t)bh * SEQ + s) * DEPTH + d] = v;
                else if (mode == 1) g_kt[((size_t)bh * DEPTH + d) * SEQ + s] = v;
                else if (mode == 2) g_v [((size_t)bh * SEQ + s) * DEPTH + d] = v;
                else                out[(size_t)m * DM + n] = v;
            }
        }
    }
}

// ---------------------------------------------------------------------------
// score_gemm: S[bh][1024q][1024k] = (Q @ K^T) * 0.125 + mask*-1e9 (in-place
// into attn buffer). 128x128 tile, K-dim=64, f32x2 microtile as above.
// ---------------------------------------------------------------------------
__global__ __launch_bounds__(256) void score_gemm(
    const float* __restrict__ mask,      // [B, S]
    float* __restrict__ attn)            // [bh, 1024, 1024]
{
    __shared__ float Asd[16][264];
    __shared__ float Bs[16][128];

    const int tid = threadIdx.x;
    const int tx = tid & 15, ty = tid >> 4;
    const int colBase = blockIdx.x * 128;     // k index
    const int rowBase = blockIdx.y * 128;     // q index
    const int bh = blockIdx.z;
    const int b  = bh >> 3;

    const float* Q  = g_q  + (size_t)bh * SEQ * DEPTH;   // [s][d]
    const float* Kt = g_kt + (size_t)bh * DEPTH * SEQ;   // [d][s]

    u64 acc[8][4];
    #pragma unroll
    for (int i = 0; i < 8; i++)
        #pragma unroll
        for (int j = 0; j < 4; j++) acc[i][j] = 0ull;

    for (int k0 = 0; k0 < DEPTH; k0 += 16) {
        #pragma unroll
        for (int i = 0; i < 2; i++) {
            int idx = tid * 2 + i;
            int r   = idx >> 2;
            int c4  = idx & 3;
            float4 v = *(const float4*)&Q[(size_t)(rowBase + r) * DEPTH + k0 + c4 * 4];
            *(float2*)&Asd[c4*4+0][2*r] = make_float2(v.x, v.x);
            *(float2*)&Asd[c4*4+1][2*r] = make_float2(v.y, v.y);
            *(float2*)&Asd[c4*4+2][2*r] = make_float2(v.z, v.z);
            *(float2*)&Asd[c4*4+3][2*r] = make_float2(v.w, v.w);
        }
        #pragma unroll
        for (int i = 0; i < 2; i++) {
            int idx = tid * 2 + i;
            int kk  = idx >> 5;
            int c4  = idx & 31;
            *(float4*)&Bs[kk][c4*4] =
                *(const float4*)&Kt[(size_t)(k0 + kk) * SEQ + colBase + c4 * 4];
        }
        __syncthreads();

        #pragma unroll
        for (int kk = 0; kk < 16; kk++) {
            U4 Aq; U2 Bq;
            Aq.f[0] = *(const float4*)&Asd[kk][ty*16 +  0];
            Aq.f[1] = *(const float4*)&Asd[kk][ty*16 +  4];
            Aq.f[2] = *(const float4*)&Asd[kk][ty*16 +  8];
            Aq.f[3] = *(const float4*)&Asd[kk][ty*16 + 12];
            Bq.f[0] = *(const float4*)&Bs[kk][tx*8];
            Bq.f[1] = *(const float4*)&Bs[kk][tx*8+4];
            #pragma unroll
            for (int i = 0; i < 8; i++)
                #pragma unroll
                for (int jp = 0; jp < 4; jp++)
                    ffma2(acc[i][jp], Aq.u[i], Bq.u[jp]);
        }
        __syncthreads();
    }

    // Epilogue: scale + mask, vectorized store
    float msk[8];
    #pragma unroll
    for (int j = 0; j < 8; j++)
        msk[j] = -1e9f * mask[b * SEQ + colBase + tx * 8 + j];

    #pragma unroll
    for (int i = 0; i < 8; i++) {
        int q = rowBase + ty * 8 + i;
        float* dst = &attn[((size_t)bh * SEQ + q) * SEQ + colBase + tx * 8];
        float o[8];
        #pragma unroll
        for (int jp = 0; jp < 4; jp++) {
            U2F c; c.u = acc[i][jp];
            o[2*jp]   = fmaf(c.f.x, 0.125f, msk[2*jp]);
            o[2*jp+1] = fmaf(c.f.y, 0.125f, msk[2*jp+1]);
        }
        *(float4*)&dst[0] = make_float4(o[0], o[1], o[2], o[3]);
        *(float4*)&dst[4] = make_float4(o[4], o[5], o[6], o[7]);
    }
}

// ---------------------------------------------------------------------------
// softmax_aw: in-place row softmax over attn then multiply by aw.
// One block per row (bh*1024+q). 256 threads, 4 elems/thread.
// ---------------------------------------------------------------------------
__global__ __launch_bounds__(256) void softmax_aw(
    const float* __restrict__ aw,        // [B, S, S]
    float* __restrict__ attn)            // [bh, 1024, 1024]
{
    __shared__ float redm[8];
    __shared__ float reds[8];

    const int row = blockIdx.x;          // bh*1024 + q
    const int bh  = row >> 10, q = row & 1023;
    const int b   = bh >> 3;
    const int t    = threadIdx.x;
    const int wid  = t >> 5, lane = t & 31;

    float* p = attn + (size_t)row * SEQ;
    const float* awr = aw + ((size_t)(b * SEQ + q)) * SEQ;

    float v[4];
    #pragma unroll
    for (int i = 0; i < 4; i++) v[i] = p[t + i * 256];

    float m = fmaxf(fmaxf(v[0], v[1]), fmaxf(v[2], v[3]));
    #pragma unroll
    for (int o = 16; o; o >>= 1) m = fmaxf(m, __shfl_xor_sync(0xffffffffu, m, o));
    if (lane == 0) redm[wid] = m;
    __syncthreads();
    float M = redm[0];
    #pragma unroll
    for (int i = 1; i < 8; i++) M = fmaxf(M, redm[i]);

    float e[4], s = 0.f;
    #pragma unroll
    for (int i = 0; i < 4; i++) { e[i] = __expf(v[i] - M); s += e[i]; }
    #pragma unroll
    for (int o = 16; o; o >>= 1) s += __shfl_xor_sync(0xffffffffu, s, o);
    if (lane == 0) reds[wid] = s;
    __syncthreads();
    float S = 0.f;
    #pragma unroll
    for (int i = 0; i < 8; i++) S += reds[i];
    const float inv = 1.f / S;

    #pragma unroll
    for (int i = 0; i < 4; i++)
        p[t + i * 256] = e[i] * inv * awr[t + i * 256];
}

// ---------------------------------------------------------------------------
// pv_gemm: X[bh][1024q][64d] = attn[bh] @ V[bh].  128x64 tile, BK=32.
// 256 threads, 8x4 microtile via f32x2 (acc pairs over d). Writes g_x.
// ---------------------------------------------------------------------------
__global__ __launch_bounds__(256) void pv_gemm(const float* __restrict__ attn)
{
    __shared__ float Asd[32][264];  // duplicated attn tile: [k][2r],[2r+1]
    __shared__ float Bs[32][64];    // [k][d]

    const int tid = threadIdx.x;
    const int tx = tid & 15, ty = tid >> 4;
    const int rowBase = blockIdx.x * 128;     // q
    const int bh = blockIdx.y;
    const int b  = bh >> 3, h = bh & 7;

    const float* A = attn + (size_t)bh * SEQ * SEQ;     // [q][k]
    const float* V = g_v  + (size_t)bh * SEQ * DEPTH;   // [k][d]

    u64 acc[8][2];
    #pragma unroll
    for (int i = 0; i < 8; i++) { acc[i][0] = 0ull; acc[i][1] = 0ull; }

    for (int k0 = 0; k0 < SEQ; k0 += 32) {
        // A tile: 128 q-rows x 32 k, duplicated (1024 float4 loads, 4/thread)
        #pragma unroll
        for (int i = 0; i < 4; i++) {
            int idx = tid * 4 + i;            // 0..1023
            int r   = idx >> 3;               // 0..127
            int c4  = idx & 7;                // 0..7
            float4 v = *(const float4*)&A[(size_t)(rowBase + r) * SEQ + k0 + c4 * 4];
            *(float2*)&Asd[c4*4+0][2*r] = make_float2(v.x, v.x);
            *(float2*)&Asd[c4*4+1][2*r] = make_float2(v.y, v.y);
            *(float2*)&Asd[c4*4+2][2*r] = make_float2(v.z, v.z);
            *(float2*)&Asd[c4*4+3][2*r] = make_float2(v.w, v.w);
        }
        // B tile: 32 k x 64 d
        #pragma unroll
        for (int i = 0; i < 2; i++) {
            int idx = tid * 2 + i;            // 0..511
            int kk  = idx >> 4;               // 0..31
            int c4  = idx & 15;               // 0..15
            *(float4*)&Bs[kk][c4*4] =
                *(const float4*)&V[(size_t)(k0 + kk) * DEPTH + c4 * 4];
        }
        __syncthreads();

        #pragma unroll
        for (int kk = 0; kk < 32; kk++) {
            U4 Aq;
            union { float4 f; u64 u[2]; } Bq;
            Aq.f[0] = *(const float4*)&Asd[kk][ty*16 +  0];
            Aq.f[1] = *(const float4*)&Asd[kk][ty*16 +  4];
            Aq.f[2] = *(const float4*)&Asd[kk][ty*16 +  8];
            Aq.f[3] = *(const float4*)&Asd[kk][ty*16 + 12];
            Bq.f = *(const float4*)&Bs[kk][tx*4];
            #pragma unroll
            for (int i = 0; i < 8; i++) {
                ffma2(acc[i][0], Aq.u[i], Bq.u[0]);
                ffma2(acc[i][1], Aq.u[i], Bq.u[1]);
            }
        }
        __syncthreads();
    }

    #pragma unroll
    for (int i = 0; i < 8; i++) {
        int q = rowBase + ty * 8 + i;
        U2F c0, c1; c0.u = acc[i][0]; c1.u = acc[i][1];
        float4 o = make_float4(c0.f.x, c0.f.y, c1.f.x, c1.f.y);
        *(float4*)&g_x[((size_t)(b * SEQ + q)) * DM + h * DEPTH + tx * 4] = o;
    }
}

// ---------------------------------------------------------------------------
extern "C" void kernel_launch(void* const* d_in, const int* in_sizes, int n_in,
                              void* d_out, int out_size)
{
    const float* q_in = (const float*)d_in[0];
    const float* k_in = (const float*)d_in[1];
    const float* v_in = (const float*)d_in[2];
    const float* mask = (const float*)d_in[3];
    const float* aw   = (const float*)d_in[4];
    const float* wq   = (const float*)d_in[5];
    const float* bq   = (const float*)d_in[6];
    const float* wk   = (const float*)d_in[7];
    const float* bk   = (const float*)d_in[8];
    const float* wv   = (const float*)d_in[9];
    const float* bv   = (const float*)d_in[10];
    const float* wo   = (const float*)d_in[11];
    const float* bo   = (const float*)d_in[12];

    float* out      = (float*)d_out;             // [8192, 512]
    float* attn_out = out + OUT_OFF;             // [8, 8, 1024, 1024]

    dim3 pgrid(DM / 128, MROWS / 128);           // (4, 64)

    proj_gemm<<<pgrid, 256>>>(q_in, wq, bq, nullptr, 0);   // Q -> g_q
    proj_gemm<<<pgrid, 256>>>(k_in, wk, bk, nullptr, 1);   // K -> g_kt
    proj_gemm<<<pgrid, 256>>>(v_in, wv, bv, nullptr, 2);   // V -> g_v

    score_gemm<<<dim3(8, 8, 64), 256>>>(mask, attn_out);   // S in-place in attn
    softmax_aw<<<BATCH * HEADS * SEQ, 256>>>(aw, attn_out);// softmax * aw in-place
    pv_gemm<<<dim3(8, 64), 256>>>(attn_out);               // X -> g_x

    proj_gemm<<<pgrid, 256>>>(nullptr, wo, bo, out, 3);    // g_x -> out
}